// round 4
// baseline (speedup 1.0000x reference)
#include <cuda_runtime.h>
#include <cstdint>

// ---------------------------------------------------------------------------
// SeqExperts: out[n,e,f] = sum_d in[n,e,d] * W[e,d,f] + b[e,f]
// N=131072, E=8, D=128.
// HMMA (mma.sync m16n8k8 tf32) with 2-MMA precision split:
//   A = rna_tf32(A) + (A - rna_tf32(A))  (exact),  W rounded once to tf32.
// tcgen05 is NOT available: harness compiles for .target sm_103 (no 'a').
// ---------------------------------------------------------------------------

#define N_TOK 131072
#define E_EXP 8
#define D_DIM 128

// Pre-transposed, RNA-rounded-to-tf32 W: g_Wt[e][f][d]  (512 KB scratch)
static __device__ __align__(16) float g_Wt[E_EXP * D_DIM * D_DIM];

__device__ __forceinline__ float rna_tf32(float v) {
    uint32_t u;
    asm("cvt.rna.tf32.f32 %0, %1;" : "=r"(u) : "f"(v));
    return __uint_as_float(u);
}

// ---------------- prep kernel: transpose + round W ----------------
__global__ void prep_w_kernel(const float* __restrict__ W) {
    int i = blockIdx.x * blockDim.x + threadIdx.x;   // 131072 elems
    int e = i >> 14;
    int d = (i >> 7) & 127;
    int f = i & 127;
    g_Wt[(e << 14) | (f << 7) | d] = rna_tf32(W[i]);
}

// ---------------- mma.sync wrapper ----------------
__device__ __forceinline__ void mma1688(float c[4], const uint32_t a[4],
                                        uint32_t b0, uint32_t b1) {
    asm volatile(
        "mma.sync.aligned.m16n8k8.row.col.f32.tf32.tf32.f32 "
        "{%0,%1,%2,%3}, {%4,%5,%6,%7}, {%8,%9}, {%0,%1,%2,%3};"
        : "+f"(c[0]), "+f"(c[1]), "+f"(c[2]), "+f"(c[3])
        : "r"(a[0]), "r"(a[1]), "r"(a[2]), "r"(a[3]), "r"(b0), "r"(b1));
}

// ---------------- SMEM layout ----------------
// Wsm [128 f][132] floats  (padded: b-frag LDS conflict-free)
// Ahi [128 m][36]  floats  (padded: a-frag LDS conflict-free)
// Alo [128 m][36]
#define WS 132
#define AS 36
#define SMEM_FLOATS (128 * WS + 2 * 128 * AS)
#define SMEM_BYTES  (SMEM_FLOATS * 4)

// ---------------- main kernel ----------------
__global__ void __launch_bounds__(256, 2)
moe_hmma_kernel(const float* __restrict__ A,
                const float* __restrict__ bias,
                float* __restrict__ out) {
    extern __shared__ float sm[];
    float* Wsm = sm;
    float* Ahi = sm + 128 * WS;
    float* Alo = Ahi + 128 * AS;

    const int tid  = threadIdx.x;
    const int wid  = tid >> 5;
    const int lane = tid & 31;
    const int e    = blockIdx.y;
    const int n0   = blockIdx.x << 7;
    const int q    = lane >> 2;   // group id (row within fragment)
    const int r    = lane & 3;    // thread in group (k / 2*col)
    const int warpM = (wid & 3) << 5;   // 0,32,64,96
    const int warpN = (wid >> 2) << 6;  // 0,64

    // ---- W tile -> smem (64 KB, coalesced float4) ----
    {
        const float4* wsrc = (const float4*)(g_Wt + (e << 14));
        #pragma unroll
        for (int i = 0; i < 16; ++i) {
            int u = tid + (i << 8);          // 0..4095 float4s
            int f = u >> 5;                  // row (32 float4 per row)
            int j = u & 31;
            float4 v = wsrc[(f << 5) + j];
            *(float4*)(Wsm + f * WS + (j << 2)) = v;
        }
    }

    float acc[2][8][4];
    #pragma unroll
    for (int mf = 0; mf < 2; ++mf)
        #pragma unroll
        for (int nf = 0; nf < 8; ++nf)
            #pragma unroll
            for (int c = 0; c < 4; ++c) acc[mf][nf][c] = 0.f;

    const float4* asrc = (const float4*)(A + ((size_t)n0 << 10) + ((size_t)e << 7));

    #pragma unroll 1
    for (int kb = 0; kb < 4; ++kb) {
        __syncthreads();   // A buffers free (prev iter consumed); kb=0: no-op ordering

        // ---- A chunk kb: 128 tokens x 32 d, split hi/lo in-flight ----
        #pragma unroll
        for (int i = 0; i < 4; ++i) {
            int u = tid + (i << 8);          // 0..1023 float4s
            int m = u >> 3;                  // token row (8 float4 per row)
            int j = u & 7;
            float4 v = asrc[(size_t)m * 256 + (kb << 3) + j];
            float4 h, l;
            h.x = rna_tf32(v.x); l.x = v.x - h.x;
            h.y = rna_tf32(v.y); l.y = v.y - h.y;
            h.z = rna_tf32(v.z); l.z = v.z - h.z;
            h.w = rna_tf32(v.w); l.w = v.w - h.w;
            *(float4*)(Ahi + m * AS + (j << 2)) = h;
            *(float4*)(Alo + m * AS + (j << 2)) = l;
        }
        __syncthreads();   // also orders W tile before first MMA

        // ---- 4 k-steps of 8 ----
        #pragma unroll
        for (int ks = 0; ks < 4; ++ks) {
            const int k0 = (kb << 5) + (ks << 3);   // k in W
            const int ka = (ks << 3);               // k in A chunk

            uint32_t b0[8], b1[8];
            #pragma unroll
            for (int nf = 0; nf < 8; ++nf) {
                const float* wp = Wsm + (warpN + (nf << 3) + q) * WS + k0 + r;
                b0[nf] = __float_as_uint(wp[0]);
                b1[nf] = __float_as_uint(wp[4]);
            }

            uint32_t ah[2][4], al[2][4];
            #pragma unroll
            for (int mf = 0; mf < 2; ++mf) {
                int m = warpM + (mf << 4) + q;
                const float* h0 = Ahi + m * AS + ka + r;
                const float* h1 = Ahi + (m + 8) * AS + ka + r;
                ah[mf][0] = __float_as_uint(h0[0]);
                ah[mf][1] = __float_as_uint(h1[0]);
                ah[mf][2] = __float_as_uint(h0[4]);
                ah[mf][3] = __float_as_uint(h1[4]);
                const float* l0 = Alo + m * AS + ka + r;
                const float* l1 = Alo + (m + 8) * AS + ka + r;
                al[mf][0] = __float_as_uint(l0[0]);
                al[mf][1] = __float_as_uint(l1[0]);
                al[mf][2] = __float_as_uint(l0[4]);
                al[mf][3] = __float_as_uint(l1[4]);
            }

            #pragma unroll
            for (int mf = 0; mf < 2; ++mf)
                #pragma unroll
                for (int nf = 0; nf < 8; ++nf) {
                    mma1688(acc[mf][nf], ah[mf], b0[nf], b1[nf]);
                    mma1688(acc[mf][nf], al[mf], b0[nf], b1[nf]);
                }
        }
    }

    // ---- epilogue: + bias, float2 stores ----
    float bv[8][2];
    #pragma unroll
    for (int nf = 0; nf < 8; ++nf) {
        int f = warpN + (nf << 3) + (r << 1);
        bv[nf][0] = __ldg(bias + (e << 7) + f);
        bv[nf][1] = __ldg(bias + (e << 7) + f + 1);
    }

    #pragma unroll
    for (int mf = 0; mf < 2; ++mf) {
        int m0 = n0 + warpM + (mf << 4) + q;
        float* o0 = out + ((size_t)m0 << 10) + ((size_t)e << 7) + warpN + (r << 1);
        float* o1 = o0 + ((size_t)8 << 10);   // row +8
        #pragma unroll
        for (int nf = 0; nf < 8; ++nf) {
            float2 v0 = { acc[mf][nf][0] + bv[nf][0], acc[mf][nf][1] + bv[nf][1] };
            float2 v1 = { acc[mf][nf][2] + bv[nf][0], acc[mf][nf][3] + bv[nf][1] };
            *(float2*)(o0 + (nf << 3)) = v0;
            *(float2*)(o1 + (nf << 3)) = v1;
        }
    }
}

// ---------------- launch ----------------
extern "C" void kernel_launch(void* const* d_in, const int* in_sizes, int n_in,
                              void* d_out, int out_size) {
    const float* A = (const float*)d_in[0];   // [N, E, D]
    const float* W = (const float*)d_in[1];   // [E, D, D]
    const float* b = (const float*)d_in[2];   // [E, D]
    float* out = (float*)d_out;               // [N, E, D]

    cudaFuncSetAttribute(moe_hmma_kernel,
                         cudaFuncAttributeMaxDynamicSharedMemorySize, SMEM_BYTES);

    prep_w_kernel<<<E_EXP * D_DIM * D_DIM / 256, 256>>>(W);

    dim3 grid(N_TOK / 128, E_EXP);
    moe_hmma_kernel<<<grid, 256, SMEM_BYTES>>>(A, b, out);
}

// round 6
// speedup vs baseline: 1.2993x; 1.2993x over previous
#include <cuda_runtime.h>
#include <cstdint>

// ---------------------------------------------------------------------------
// SeqExperts: out[n,e,f] = sum_d in[n,e,d] * W[e,d,f] + b[e,f]
// N=131072, E=8, D=128.
// HMMA mma.sync m16n8k8 tf32, single-MMA (A and W each RNA-rounded to tf32).
// Measured: W rounding alone -> 2.16e-4; adding A rounding -> ~3.1e-4 < 1e-3.
// Pair-interleaved smem layouts: (d, d+4) adjacent => all frag loads LDS.64.
// ---------------------------------------------------------------------------

#define N_TOK 131072
#define E_EXP 8
#define D_DIM 128

// W in pair layout: for (e,f): 64 float2 pairs, pair p=(g*4+r) = (d=g*8+r, d+4)
// flattened float index within row: p*2 + slot
static __device__ __align__(16) float g_Wt[E_EXP * D_DIM * D_DIM];

__device__ __forceinline__ float rna_tf32(float v) {
    uint32_t u;
    asm("cvt.rna.tf32.f32 %0, %1;" : "=r"(u) : "f"(v));
    return __uint_as_float(u);
}

// ---------------- prep: transpose + round + pair-interleave W ----------------
__global__ void prep_w_kernel(const float* __restrict__ W) {
    int i = blockIdx.x * blockDim.x + threadIdx.x;   // 131072, coalesced read
    int e = i >> 14;
    int d = (i >> 7) & 127;
    int f = i & 127;
    // dest float index within (e,f) row of 128 floats:
    //   pair p = (d>>3)*4 + (d&3), slot = (d>>2)&1  ->  idx = p*2 + slot
    int idx = ((d >> 3) << 3) + ((d & 3) << 1) + ((d >> 2) & 1);
    g_Wt[(((e << 7) | f) << 7) + idx] = rna_tf32(W[i]);
}

// ---------------- mma.sync wrapper ----------------
__device__ __forceinline__ void mma1688(float c[4], uint32_t a0, uint32_t a1,
                                        uint32_t a2, uint32_t a3,
                                        uint32_t b0, uint32_t b1) {
    asm volatile(
        "mma.sync.aligned.m16n8k8.row.col.f32.tf32.tf32.f32 "
        "{%0,%1,%2,%3}, {%4,%5,%6,%7}, {%8,%9}, {%0,%1,%2,%3};"
        : "+f"(c[0]), "+f"(c[1]), "+f"(c[2]), "+f"(c[3])
        : "r"(a0), "r"(a1), "r"(a2), "r"(a3), "r"(b0), "r"(b1));
}

// ---------------- SMEM layout (float strides chosen: stride mod 32 == 8) ----
#define WSF 136   // floats per W row (64 pairs + pad)   -> conflict-free LDS.64
#define ASF 40    // floats per A row (16 pairs + pad)   -> conflict-free LDS.64
#define SMEM_BYTES ((128 * WSF + 128 * ASF) * 4)   // 69632 + 20480 = 90112 B

// ---------------- main kernel ----------------
__global__ void __launch_bounds__(256, 2)
moe_hmma_kernel(const float* __restrict__ A,
                const float* __restrict__ bias,
                float* __restrict__ out) {
    extern __shared__ float sm[];
    float* Wsm = sm;                 // [128 f][WSF]
    float* Asm = sm + 128 * WSF;     // [128 m][ASF]

    const int tid  = threadIdx.x;
    const int wid  = tid >> 5;
    const int lane = tid & 31;
    const int e    = blockIdx.y;
    const int n0   = blockIdx.x << 7;
    const int q    = lane >> 2;          // group (row in frag)
    const int r    = lane & 3;           // thread-in-group
    const int warpM = (wid & 3) << 5;    // 0,32,64,96
    const int warpN = (wid >> 2) << 6;   // 0,64

    // ---- W tile -> smem (coalesced float4 copy of pair-layout rows) ----
    {
        const float4* wsrc = (const float4*)(g_Wt + (e << 14));
        #pragma unroll
        for (int i = 0; i < 16; ++i) {
            int u = tid + (i << 8);          // 0..4095 float4s
            int f = u >> 5;                  // 32 float4 per row
            int j = u & 31;
            *(float4*)(Wsm + f * WSF + (j << 2)) = wsrc[(f << 5) + j];
        }
    }

    float acc[2][8][4];
    #pragma unroll
    for (int mf = 0; mf < 2; ++mf)
        #pragma unroll
        for (int nf = 0; nf < 8; ++nf)
            #pragma unroll
            for (int c = 0; c < 4; ++c) acc[mf][nf][c] = 0.f;

    const float4* asrc = (const float4*)(A + ((size_t)n0 << 10) + ((size_t)e << 7));

    #pragma unroll 1
    for (int kb = 0; kb < 4; ++kb) {
        __syncthreads();   // previous chunk fully consumed

        // ---- A chunk kb: 128 tokens x 32 d -> rounded tf32 pairs in smem ----
        // thread handles 2 chunks of 8 d's: c = tid, tid+256; m=c>>2, gl=c&3
        #pragma unroll
        for (int i = 0; i < 2; ++i) {
            int c  = tid + (i << 8);
            int m  = c >> 2;
            int gl = c & 3;
            const float4* p = asrc + (size_t)m * 256 + (kb << 3) + (gl << 1);
            float4 v0 = p[0];
            float4 v1 = p[1];
            float* dst = Asm + m * ASF + (gl << 3);
            float4 s0, s1;
            s0.x = rna_tf32(v0.x); s0.y = rna_tf32(v1.x);
            s0.z = rna_tf32(v0.y); s0.w = rna_tf32(v1.y);
            s1.x = rna_tf32(v0.z); s1.y = rna_tf32(v1.z);
            s1.z = rna_tf32(v0.w); s1.w = rna_tf32(v1.w);
            *(float4*)(dst)     = s0;   // pairs (d+0,d+4),(d+1,d+5)
            *(float4*)(dst + 4) = s1;   // pairs (d+2,d+6),(d+3,d+7)
        }
        __syncthreads();

        // ---- 4 k-steps of 8 ----
        #pragma unroll
        for (int ks = 0; ks < 4; ++ks) {
            const int g = (kb << 2) + ks;        // global k-group for W pairs

            // b-frags: 8 x LDS.64, conflict-free
            float2 b[8];
            #pragma unroll
            for (int nf = 0; nf < 8; ++nf)
                b[nf] = *(const float2*)(Wsm + (warpN + (nf << 3) + q) * WSF
                                             + ((g << 2) + r) * 2);

            // a-frags: 4 x LDS.64, conflict-free
            float2 a0[2], a1[2];
            #pragma unroll
            for (int mf = 0; mf < 2; ++mf) {
                int m = warpM + (mf << 4) + q;
                a0[mf] = *(const float2*)(Asm + m * ASF + ((ks << 2) + r) * 2);
                a1[mf] = *(const float2*)(Asm + (m + 8) * ASF + ((ks << 2) + r) * 2);
            }

            #pragma unroll
            for (int mf = 0; mf < 2; ++mf)
                #pragma unroll
                for (int nf = 0; nf < 8; ++nf)
                    mma1688(acc[mf][nf],
                            __float_as_uint(a0[mf].x), __float_as_uint(a1[mf].x),
                            __float_as_uint(a0[mf].y), __float_as_uint(a1[mf].y),
                            __float_as_uint(b[nf].x),  __float_as_uint(b[nf].y));
        }
    }

    // ---- epilogue: + bias, float2 stores ----
    float bv[8][2];
    #pragma unroll
    for (int nf = 0; nf < 8; ++nf) {
        int f = warpN + (nf << 3) + (r << 1);
        bv[nf][0] = __ldg(bias + (e << 7) + f);
        bv[nf][1] = __ldg(bias + (e << 7) + f + 1);
    }

    #pragma unroll
    for (int mf = 0; mf < 2; ++mf) {
        int m0 = n0 + warpM + (mf << 4) + q;
        float* o0 = out + ((size_t)m0 << 10) + ((size_t)e << 7) + warpN + (r << 1);
        float* o1 = o0 + ((size_t)8 << 10);   // row +8
        #pragma unroll
        for (int nf = 0; nf < 8; ++nf) {
            float2 v0 = { acc[mf][nf][0] + bv[nf][0], acc[mf][nf][1] + bv[nf][1] };
            float2 v1 = { acc[mf][nf][2] + bv[nf][0], acc[mf][nf][3] + bv[nf][1] };
            *(float2*)(o0 + (nf << 3)) = v0;
            *(float2*)(o1 + (nf << 3)) = v1;
        }
    }
}

// ---------------- launch ----------------
extern "C" void kernel_launch(void* const* d_in, const int* in_sizes, int n_in,
                              void* d_out, int out_size) {
    const float* A = (const float*)d_in[0];   // [N, E, D]
    const float* W = (const float*)d_in[1];   // [E, D, D]
    const float* b = (const float*)d_in[2];   // [E, D]
    float* out = (float*)d_out;               // [N, E, D]

    cudaFuncSetAttribute(moe_hmma_kernel,
                         cudaFuncAttributeMaxDynamicSharedMemorySize, SMEM_BYTES);

    prep_w_kernel<<<E_EXP * D_DIM * D_DIM / 256, 256>>>(W);

    dim3 grid(N_TOK / 128, E_EXP);
    moe_hmma_kernel<<<grid, 256, SMEM_BYTES>>>(A, b, out);
}

// round 9
// speedup vs baseline: 1.6902x; 1.3008x over previous
#include <cuda_runtime.h>
#include <cstdint>

// ---------------------------------------------------------------------------
// SeqExperts: out[n,e,f] = sum_d in[n,e,d] * W[e,d,f] + b[e,f]
// N=131072, E=8, D=128.
// mma.sync m16n8k8 tf32; A and W each RNA-rounded once (rel_err ~3e-4).
// R8: fixes R6's prologue OOB (chunk-1 dst offset); cp.async + double-buffered
//     A chunks; A rounded at fragment-load time; pair-interleaved W (LDS.64).
// ---------------------------------------------------------------------------

#define N_TOK 131072
#define E_EXP 8
#define D_DIM 128

// W pre-transposed + RNA-rounded + pair-interleaved: row (e,f) holds 64
// float2 pairs; pair p=(d>>3)*4+(d&3) holds (W[d], W[d+4]), d=8*(p>>2)+(p&3)
static __device__ __align__(16) float g_Wt[E_EXP * D_DIM * D_DIM];

__device__ __forceinline__ float rna_tf32(float v) {
    uint32_t u;
    asm("cvt.rna.tf32.f32 %0, %1;" : "=r"(u) : "f"(v));
    return __uint_as_float(u);
}

__device__ __forceinline__ uint32_t smem_u32(const void* p) {
    uint32_t a;
    asm("{ .reg .u64 t; cvta.to.shared.u64 t, %1; cvt.u32.u64 %0, t; }"
        : "=r"(a) : "l"(p));
    return a;
}

__device__ __forceinline__ void cp16(uint32_t dst, const void* src) {
    asm volatile("cp.async.cg.shared.global [%0], [%1], 16;"
                 :: "r"(dst), "l"(src) : "memory");
}
#define CP_COMMIT() asm volatile("cp.async.commit_group;" ::: "memory")
template <int N>
__device__ __forceinline__ void cp_wait() {
    asm volatile("cp.async.wait_group %0;" :: "n"(N) : "memory");
}

// ---------------- prep: transpose + round + pair-interleave W ----------------
__global__ void prep_w_kernel(const float* __restrict__ W) {
    int i = blockIdx.x * blockDim.x + threadIdx.x;   // 131072, coalesced read
    int e = i >> 14;
    int d = (i >> 7) & 127;
    int f = i & 127;
    int idx = ((d >> 3) << 3) + ((d & 3) << 1) + ((d >> 2) & 1);
    g_Wt[(((e << 7) | f) << 7) + idx] = rna_tf32(W[i]);
}

// ---------------- mma.sync wrapper ----------------
__device__ __forceinline__ void mma1688(float c[4], float a0, float a1,
                                        float a2, float a3, float b0, float b1) {
    asm volatile(
        "mma.sync.aligned.m16n8k8.row.col.f32.tf32.tf32.f32 "
        "{%0,%1,%2,%3}, {%4,%5,%6,%7}, {%8,%9}, {%0,%1,%2,%3};"
        : "+f"(c[0]), "+f"(c[1]), "+f"(c[2]), "+f"(c[3])
        : "r"(__float_as_uint(a0)), "r"(__float_as_uint(a1)),
          "r"(__float_as_uint(a2)), "r"(__float_as_uint(a3)),
          "r"(__float_as_uint(b0)), "r"(__float_as_uint(b1)));
}

// ---------------- SMEM layout ----------------
#define WSF 136   // floats per W row; 136 mod 32 = 8  -> LDS.64 conflict-free
#define ASF 36    // floats per A row; 36 mod 32 = 4   -> LDS.32 conflict-free
#define SM_A0 (128 * WSF)                    // float offsets
#define SM_A1 (SM_A0 + 128 * ASF)
#define SMEM_BYTES ((SM_A1 + 128 * ASF) * 4) // 69632 + 2*18432 = 106496 B

// ---------------- main kernel ----------------
__global__ void __launch_bounds__(256, 2)
moe_hmma_kernel(const float* __restrict__ A,
                const float* __restrict__ bias,
                float* __restrict__ out) {
    extern __shared__ float sm[];
    float* Wsm = sm;
    float* Ab[2] = { sm + SM_A0, sm + SM_A1 };

    const int tid  = threadIdx.x;
    const int wid  = tid >> 5;
    const int lane = tid & 31;
    const int e    = blockIdx.y;
    const int n0   = blockIdx.x << 7;
    const int q    = lane >> 2;          // frag row group
    const int r    = lane & 3;           // thread-in-group
    const int warpM = (wid & 3) << 5;    // 0,32,64,96
    const int warpN = (wid >> 2) << 6;   // 0,64

    const uint32_t sW = smem_u32(Wsm);
    const uint32_t sA[2] = { smem_u32(Ab[0]), smem_u32(Ab[1]) };
    const char* abase = (const char*)A + (size_t)n0 * 4096 + (size_t)e * 512;

    // ---- prologue: W tile + A chunk0 (group0); A chunk1 (group1) ----
    {
        const char* wsrc = (const char*)(g_Wt + (e << 14));
        #pragma unroll
        for (int i = 0; i < 16; ++i) {
            int u = tid + (i << 8);           // 0..4095 16B units
            int f = u >> 5;
            int j = u & 31;
            cp16(sW + f * 544 + (j << 4), wsrc + (size_t)f * 512 + (j << 4));
        }
    }
    #pragma unroll
    for (int i = 0; i < 4; ++i) {             // A chunk 0 -> buf0 row starts
        int u = tid + (i << 8);
        int m = u >> 3, j = u & 7;
        cp16(sA[0] + m * 144 + (j << 4), abase + (size_t)m * 4096 + (j << 4));
    }
    CP_COMMIT();                              // group 0
    #pragma unroll
    for (int i = 0; i < 4; ++i) {             // A chunk 1 -> buf1 row starts
        int u = tid + (i << 8);
        int m = u >> 3, j = u & 7;
        cp16(sA[1] + m * 144 + (j << 4),      // dst at row start (R6 bug fixed)
             abase + (size_t)m * 4096 + 128 + (j << 4));
    }
    CP_COMMIT();                              // group 1

    float acc[2][8][4];
    #pragma unroll
    for (int mf = 0; mf < 2; ++mf)
        #pragma unroll
        for (int nf = 0; nf < 8; ++nf)
            #pragma unroll
            for (int c = 0; c < 4; ++c) acc[mf][nf][c] = 0.f;

    #pragma unroll
    for (int kb = 0; kb < 4; ++kb) {
        if (kb < 3) cp_wait<1>(); else cp_wait<0>();
        __syncthreads();

        const float* Ac = Ab[kb & 1];

        // ---- compute chunk kb ----
        #pragma unroll
        for (int ks = 0; ks < 4; ++ks) {
            const int g = (kb << 2) + ks;

            float2 b[8];
            #pragma unroll
            for (int nf = 0; nf < 8; ++nf)
                b[nf] = *(const float2*)(Wsm + (warpN + (nf << 3) + q) * WSF
                                             + ((g << 2) + r) * 2);

            float a0[2], a1[2], a2[2], a3[2];
            #pragma unroll
            for (int mf = 0; mf < 2; ++mf) {
                int m = warpM + (mf << 4) + q;
                const float* ap  = Ac + m * ASF + (ks << 3) + r;
                const float* ap8 = ap + 8 * ASF;
                a0[mf] = rna_tf32(ap[0]);
                a1[mf] = rna_tf32(ap8[0]);
                a2[mf] = rna_tf32(ap[4]);
                a3[mf] = rna_tf32(ap8[4]);
            }

            #pragma unroll
            for (int mf = 0; mf < 2; ++mf)
                #pragma unroll
                for (int nf = 0; nf < 8; ++nf)
                    mma1688(acc[mf][nf], a0[mf], a1[mf], a2[mf], a3[mf],
                            b[nf].x, b[nf].y);
        }

        // ---- prefetch chunk kb+2 into the buffer just consumed ----
        if (kb < 2) {
            __syncthreads();
            const int kn = kb + 2;
            #pragma unroll
            for (int i = 0; i < 4; ++i) {
                int u = tid + (i << 8);
                int m = u >> 3, j = u & 7;
                cp16(sA[kb & 1] + m * 144 + (j << 4),
                     abase + (size_t)m * 4096 + (size_t)kn * 128 + (j << 4));
            }
            CP_COMMIT();
        }
    }

    // ---- epilogue: + bias, float2 stores ----
    float bv[8][2];
    #pragma unroll
    for (int nf = 0; nf < 8; ++nf) {
        int f = warpN + (nf << 3) + (r << 1);
        bv[nf][0] = __ldg(bias + (e << 7) + f);
        bv[nf][1] = __ldg(bias + (e << 7) + f + 1);
    }

    #pragma unroll
    for (int mf = 0; mf < 2; ++mf) {
        int m0 = n0 + warpM + (mf << 4) + q;
        float* o0 = out + ((size_t)m0 << 10) + ((size_t)e << 7) + warpN + (r << 1);
        float* o1 = o0 + ((size_t)8 << 10);
        #pragma unroll
        for (int nf = 0; nf < 8; ++nf) {
            float2 v0 = { acc[mf][nf][0] + bv[nf][0], acc[mf][nf][1] + bv[nf][1] };
            float2 v1 = { acc[mf][nf][2] + bv[nf][0], acc[mf][nf][3] + bv[nf][1] };
            *(float2*)(o0 + (nf << 3)) = v0;
            *(float2*)(o1 + (nf << 3)) = v1;
        }
    }
}

// ---------------- launch ----------------
extern "C" void kernel_launch(void* const* d_in, const int* in_sizes, int n_in,
                              void* d_out, int out_size) {
    const float* A = (const float*)d_in[0];   // [N, E, D]
    const float* W = (const float*)d_in[1];   // [E, D, D]
    const float* b = (const float*)d_in[2];   // [E, D]
    float* out = (float*)d_out;               // [N, E, D]

    cudaFuncSetAttribute(moe_hmma_kernel,
                         cudaFuncAttributeMaxDynamicSharedMemorySize, SMEM_BYTES);

    prep_w_kernel<<<E_EXP * D_DIM * D_DIM / 256, 256>>>(W);

    dim3 grid(N_TOK / 128, E_EXP);
    moe_hmma_kernel<<<grid, 256, SMEM_BYTES>>>(A, b, out);
}

// round 11
// speedup vs baseline: 1.9316x; 1.1428x over previous
#include <cuda_runtime.h>
#include <cstdint>

// ---------------------------------------------------------------------------
// SeqExperts: out[n,e,f] = sum_d in[n,e,d] * W[e,d,f] + b[e,f]
// N=131072, E=8, D=128.
// mma.sync m16n8k8 tf32; A and W each RNA-rounded once (rel_err ~3e-4).
// R9: triple-buffered A + single barrier per chunk (prefetch overlaps compute);
//     XOR-swizzled unpadded smem (W 64KB, A 3x16KB) -> 112KB/CTA, 2 CTAs/SM.
// ---------------------------------------------------------------------------

#define N_TOK 131072
#define E_EXP 8
#define D_DIM 128

// W pre-transposed + RNA-rounded + pair-interleaved: row (e,f) holds 64
// float2 pairs; pair p=4g+r holds (W[d], W[d+4]) with d=8g+r.
static __device__ __align__(16) float g_Wt[E_EXP * D_DIM * D_DIM];

__device__ __forceinline__ float rna_tf32(float v) {
    uint32_t u;
    asm("cvt.rna.tf32.f32 %0, %1;" : "=r"(u) : "f"(v));
    return __uint_as_float(u);
}

__device__ __forceinline__ uint32_t smem_u32(const void* p) {
    uint32_t a;
    asm("{ .reg .u64 t; cvta.to.shared.u64 t, %1; cvt.u32.u64 %0, t; }"
        : "=r"(a) : "l"(p));
    return a;
}

__device__ __forceinline__ void cp16(uint32_t dst, const void* src) {
    asm volatile("cp.async.cg.shared.global [%0], [%1], 16;"
                 :: "r"(dst), "l"(src) : "memory");
}
#define CP_COMMIT() asm volatile("cp.async.commit_group;" ::: "memory")
template <int N>
__device__ __forceinline__ void cp_wait() {
    asm volatile("cp.async.wait_group %0;" :: "n"(N) : "memory");
}

// ---------------- prep: transpose + round + pair-interleave W ----------------
__global__ void prep_w_kernel(const float* __restrict__ W) {
    int i = blockIdx.x * blockDim.x + threadIdx.x;   // 131072, coalesced read
    int e = i >> 14;
    int d = (i >> 7) & 127;
    int f = i & 127;
    int idx = ((d >> 3) << 3) + ((d & 3) << 1) + ((d >> 2) & 1);
    g_Wt[(((e << 7) | f) << 7) + idx] = rna_tf32(W[i]);
}

// ---------------- mma.sync wrapper ----------------
__device__ __forceinline__ void mma1688(float c[4], float a0, float a1,
                                        float a2, float a3, float b0, float b1) {
    asm volatile(
        "mma.sync.aligned.m16n8k8.row.col.f32.tf32.tf32.f32 "
        "{%0,%1,%2,%3}, {%4,%5,%6,%7}, {%8,%9}, {%0,%1,%2,%3};"
        : "+f"(c[0]), "+f"(c[1]), "+f"(c[2]), "+f"(c[3])
        : "r"(__float_as_uint(a0)), "r"(__float_as_uint(a1)),
          "r"(__float_as_uint(a2)), "r"(__float_as_uint(a3)),
          "r"(__float_as_uint(b0)), "r"(__float_as_uint(b1)));
}

// ---------------- SMEM layout (swizzled, no padding) ----------------
// W: 128 rows x 512B (128 floats). 8B elt e at e ^ (4*(f&7)).   64 KB
// A: 3 bufs of 128 rows x 128B (32 floats). 8B elt e at e ^ (2*(m&7)). 16 KB ea
#define SM_A0 (128 * 128)                       // float offset of A buf 0
#define ABUF_FLOATS (128 * 32)
#define SMEM_BYTES ((SM_A0 + 3 * ABUF_FLOATS) * 4)   // 114688 B

// ---------------- main kernel ----------------
__global__ void __launch_bounds__(256, 2)
moe_hmma_kernel(const float* __restrict__ A,
                const float* __restrict__ bias,
                float* __restrict__ out) {
    extern __shared__ float sm[];
    float* Wsm = sm;

    const int tid  = threadIdx.x;
    const int wid  = tid >> 5;
    const int lane = tid & 31;
    const int e    = blockIdx.y;
    const int n0   = blockIdx.x << 7;
    const int q    = lane >> 2;          // frag row group
    const int r    = lane & 3;           // thread-in-group
    const int warpM = (wid & 3) << 5;    // 0,32,64,96
    const int warpN = (wid >> 2) << 6;   // 0,64

    const uint32_t sW = smem_u32(sm);
    const uint32_t sA[3] = { sW + SM_A0 * 4,
                             sW + (SM_A0 + ABUF_FLOATS) * 4,
                             sW + (SM_A0 + 2 * ABUF_FLOATS) * 4 };
    const char* abase = (const char*)A + (size_t)n0 * 4096 + (size_t)e * 512;

    // ---- prologue: W + A chunk0 (group0); A chunk1 (group1) ----
    {
        const char* wsrc = (const char*)(g_Wt + (e << 14));
        #pragma unroll
        for (int i = 0; i < 16; ++i) {
            int u = tid + (i << 8);               // 0..4095 16B units
            int f = u >> 5;
            int j = u & 31;
            int js = j ^ ((f & 7) << 1);          // 16B-unit swizzle
            cp16(sW + f * 512 + (js << 4), wsrc + (size_t)f * 512 + (j << 4));
        }
    }
    #pragma unroll
    for (int i = 0; i < 4; ++i) {                 // chunk 0 -> buf 0
        int u = tid + (i << 8);
        int m = u >> 3, j = u & 7;
        int js = j ^ (m & 7);
        cp16(sA[0] + m * 128 + (js << 4), abase + (size_t)m * 4096 + (j << 4));
    }
    CP_COMMIT();                                  // group 0
    #pragma unroll
    for (int i = 0; i < 4; ++i) {                 // chunk 1 -> buf 1
        int u = tid + (i << 8);
        int m = u >> 3, j = u & 7;
        int js = j ^ (m & 7);
        cp16(sA[1] + m * 128 + (js << 4),
             abase + (size_t)m * 4096 + 128 + (j << 4));
    }
    CP_COMMIT();                                  // group 1

    float acc[2][8][4];
    #pragma unroll
    for (int mf = 0; mf < 2; ++mf)
        #pragma unroll
        for (int nf = 0; nf < 8; ++nf)
            #pragma unroll
            for (int c = 0; c < 4; ++c) acc[mf][nf][c] = 0.f;

    const int wsw = q << 2;                       // W 8B-elt swizzle for my rows
    const int asw = q << 1;                       // A 8B-elt swizzle for my rows

    #pragma unroll
    for (int kb = 0; kb < 4; ++kb) {
        if (kb < 3) cp_wait<1>(); else cp_wait<0>();
        __syncthreads();                          // chunk kb ready; buf (kb+2)%3 free

        // issue prefetch of chunk kb+2 (overlaps with compute below)
        if (kb < 2) {
            const int kn = kb + 2;
            #pragma unroll
            for (int i = 0; i < 4; ++i) {
                int u = tid + (i << 8);
                int m = u >> 3, j = u & 7;
                int js = j ^ (m & 7);
                cp16(sA[kn % 3] + m * 128 + (js << 4),
                     abase + (size_t)m * 4096 + (size_t)kn * 128 + (j << 4));
            }
            CP_COMMIT();
        }

        const float* Ac = (const float*)(size_t)0;  // unused; address via sA
        const float* Abuf = sm + SM_A0 + (kb % 3) * ABUF_FLOATS;

        // ---- compute chunk kb ----
        #pragma unroll
        for (int ks = 0; ks < 4; ++ks) {
            const int g = (kb << 2) + ks;

            float2 b[8];
            #pragma unroll
            for (int nf = 0; nf < 8; ++nf) {
                int f  = warpN + (nf << 3) + q;
                int ep = ((g << 2) + r) ^ wsw;     // swizzled 8B elt
                b[nf] = *(const float2*)(Wsm + (f << 7) + (ep << 1));
            }

            float a0[2], a1[2], a2[2], a3[2];
            const int eb   = (ks << 2) + (r >> 1); // 8B elt of col 8ks+r
            const int half = r & 1;
            const int i0 = (((eb)     ^ asw) << 1) + half;
            const int i2 = (((eb + 2) ^ asw) << 1) + half;
            #pragma unroll
            for (int mf = 0; mf < 2; ++mf) {
                int m = warpM + (mf << 4) + q;
                const float* rp  = Abuf + (m << 5);
                const float* rp8 = Abuf + ((m + 8) << 5);
                a0[mf] = rna_tf32(rp[i0]);
                a1[mf] = rna_tf32(rp8[i0]);
                a2[mf] = rna_tf32(rp[i2]);
                a3[mf] = rna_tf32(rp8[i2]);
            }

            #pragma unroll
            for (int mf = 0; mf < 2; ++mf)
                #pragma unroll
                for (int nf = 0; nf < 8; ++nf)
                    mma1688(acc[mf][nf], a0[mf], a1[mf], a2[mf], a3[mf],
                            b[nf].x, b[nf].y);
        }
        (void)Ac;
    }

    // ---- epilogue: + bias, float2 stores ----
    float bv[8][2];
    #pragma unroll
    for (int nf = 0; nf < 8; ++nf) {
        int f = warpN + (nf << 3) + (r << 1);
        bv[nf][0] = __ldg(bias + (e << 7) + f);
        bv[nf][1] = __ldg(bias + (e << 7) + f + 1);
    }

    #pragma unroll
    for (int mf = 0; mf < 2; ++mf) {
        int m0 = n0 + warpM + (mf << 4) + q;
        float* o0 = out + ((size_t)m0 << 10) + ((size_t)e << 7) + warpN + (r << 1);
        float* o1 = o0 + ((size_t)8 << 10);
        #pragma unroll
        for (int nf = 0; nf < 8; ++nf) {
            float2 v0 = { acc[mf][nf][0] + bv[nf][0], acc[mf][nf][1] + bv[nf][1] };
            float2 v1 = { acc[mf][nf][2] + bv[nf][0], acc[mf][nf][3] + bv[nf][1] };
            *(float2*)(o0 + (nf << 3)) = v0;
            *(float2*)(o1 + (nf << 3)) = v1;
        }
    }
}

// ---------------- launch ----------------
extern "C" void kernel_launch(void* const* d_in, const int* in_sizes, int n_in,
                              void* d_out, int out_size) {
    const float* A = (const float*)d_in[0];   // [N, E, D]
    const float* W = (const float*)d_in[1];   // [E, D, D]
    const float* b = (const float*)d_in[2];   // [E, D]
    float* out = (float*)d_out;               // [N, E, D]

    cudaFuncSetAttribute(moe_hmma_kernel,
                         cudaFuncAttributeMaxDynamicSharedMemorySize, SMEM_BYTES);

    prep_w_kernel<<<E_EXP * D_DIM * D_DIM / 256, 256>>>(W);

    dim3 grid(N_TOK / 128, E_EXP);
    moe_hmma_kernel<<<grid, 256, SMEM_BYTES>>>(A, b, out);
}